// round 16
// baseline (speedup 1.0000x reference)
#include <cuda_runtime.h>
#include <cuda_fp16.h>

// LightGCN, y-space formulation with fp16 intermediates + PADDED CSR.
//   Each node owns CAP slots in g_cols; scatter = cursor atomics from 0;
//   deg = final cursor value (no histogram, no scans).
//   y0' = fp16(emb) (plain);  layer1 applies dinv per edge:
//     y1 = dinv^2 * sum(dinv[d] * y0'[d]);  y2 = dinv^2 * sum(y1[d])
//   out = (emb + rinv*y1 + rinv*y2 + dinv*sum(y2[d])) / 4, emb exact fp32.
// g_cursor self-resets in spmm_last for graph replays.

#define D 128
#define MAX_NODES 160000
#define CAP 96                      // max degree headroom (Poisson(20) tail << 96)

struct __align__(8) Half4 {
    __half2 h01;
    __half2 h23;
};

__device__ int   g_cursor[MAX_NODES];       // zeroed at load; reset by spmm_last
__device__ float g_dinv[MAX_NODES];
__device__ float g_rinv[MAX_NODES];
__device__ int   g_cols[(size_t)MAX_NODES * CAP];
__device__ Half4 g_y0[(size_t)MAX_NODES * 32];   // fp16(emb), no dinv
__device__ Half4 g_y1[(size_t)MAX_NODES * 32];
__device__ Half4 g_y2[(size_t)MAX_NODES * 32];

// ---------------------------------------------------------------- setup ----

// FIRST kernel (no predecessors): scatter into padded slots + plain convert.
//   threads [0, nscat)   : 4 edges each (int4), cursor atomics from zero
//   threads [nscat, ...) : one Half4 convert each: y0' = fp16(emb)
__global__ void scatcvt_kernel(const float* __restrict__ uw,
                               const float* __restrict__ iw,
                               const int* __restrict__ src,
                               const int* __restrict__ dst,
                               int nE, int nscat, int num_users, int n_nodes) {
    int i = blockIdx.x * blockDim.x + threadIdx.x;

    if (i < nscat) {
        int e = i * 4;
        if (e + 3 < nE) {
            int4 s4 = __ldg((const int4*)(src + e));
            int4 d4 = __ldg((const int4*)(dst + e));
            int p0 = atomicAdd(&g_cursor[s4.x], 1);
            int p1 = atomicAdd(&g_cursor[s4.y], 1);
            int p2 = atomicAdd(&g_cursor[s4.z], 1);
            int p3 = atomicAdd(&g_cursor[s4.w], 1);
            g_cols[(size_t)s4.x * CAP + p0] = d4.x;
            g_cols[(size_t)s4.y * CAP + p1] = d4.y;
            g_cols[(size_t)s4.z * CAP + p2] = d4.z;
            g_cols[(size_t)s4.w * CAP + p3] = d4.w;
        } else {
            for (int k = e; k < nE; k++) {
                int s = src[k];
                int pos = atomicAdd(&g_cursor[s], 1);
                g_cols[(size_t)s * CAP + pos] = dst[k];
            }
        }
        return;
    }

    int j = i - nscat;
    if (j >= n_nodes * 32) return;
    int node = j >> 5, lane = j & 31;
    const float4* srcp = (const float4*)((node < num_users)
                            ? uw + (size_t)node * D
                            : iw + (size_t)(node - num_users) * D);
    float4 f = srcp[lane];
    Half4 r;
    r.h01 = __floats2half2_rn(f.x, f.y);
    r.h23 = __floats2half2_rn(f.z, f.w);
    g_y0[j] = r;
}

// dinv/rinv from the final cursor values (= degree incl. duplicates)
__global__ void dinv_kernel(int n) {
    int i = blockIdx.x * blockDim.x + threadIdx.x;
    if (i < n) {
        int d = g_cursor[i];
        float fd = (float)d;
        g_dinv[i] = (d > 0) ? rsqrtf(fd) : 0.0f;
        g_rinv[i] = (d > 0) ? sqrtf(fd) : 0.0f;
    }
}

// ----------------------------------------------------------------- SpMM ----
// One warp per row; lane owns dims [4*lane, 4*lane+4) as one Half4.

__device__ __forceinline__ void acc_edge(Half4 r,
                                         float& a0, float& a1, float& a2, float& a3) {
    float2 f01 = __half22float2(r.h01);
    float2 f23 = __half22float2(r.h23);
    a0 += f01.x;
    a1 += f01.y;
    a2 += f23.x;
    a3 += f23.y;
}

__device__ __forceinline__ void acc_edge_w(float v, Half4 r,
                                           float& a0, float& a1, float& a2, float& a3) {
    float2 f01 = __half22float2(r.h01);
    float2 f23 = __half22float2(r.h23);
    a0 = fmaf(v, f01.x, a0);
    a1 = fmaf(v, f01.y, a1);
    a2 = fmaf(v, f23.x, a2);
    a3 = fmaf(v, f23.y, a3);
}

// unweighted gather (layers 2,3): 16-edge unroll
__device__ __forceinline__ void gather_row(const Half4* __restrict__ xin,
                                           const int* __restrict__ crow,
                                           int deg, int lane,
                                           float& a0, float& a1, float& a2, float& a3) {
    int j = 0;
    for (; j + 16 <= deg; j += 16) {
        int c[16];
#pragma unroll
        for (int k = 0; k < 16; k++) c[k] = __ldg(&crow[j + k]);
        Half4 r[16];
#pragma unroll
        for (int k = 0; k < 16; k++) r[k] = xin[(size_t)c[k] * 32 + lane];
#pragma unroll
        for (int k = 0; k < 16; k++) acc_edge(r[k], a0, a1, a2, a3);
    }
    for (; j + 4 <= deg; j += 4) {
        int c0 = __ldg(&crow[j]);
        int c1 = __ldg(&crow[j + 1]);
        int c2 = __ldg(&crow[j + 2]);
        int c3 = __ldg(&crow[j + 3]);
        Half4 r0 = xin[(size_t)c0 * 32 + lane];
        Half4 r1 = xin[(size_t)c1 * 32 + lane];
        Half4 r2 = xin[(size_t)c2 * 32 + lane];
        Half4 r3 = xin[(size_t)c3 * 32 + lane];
        acc_edge(r0, a0, a1, a2, a3);
        acc_edge(r1, a0, a1, a2, a3);
        acc_edge(r2, a0, a1, a2, a3);
        acc_edge(r3, a0, a1, a2, a3);
    }
    for (; j < deg; j++) {
        int c = __ldg(&crow[j]);
        Half4 r = xin[(size_t)c * 32 + lane];
        acc_edge(r, a0, a1, a2, a3);
    }
}

// layer 1: weighted gather of y0' with per-edge dinv; y1 = dinv^2 * sum
__global__ void __launch_bounds__(256)
spmm_l1(int n_nodes) {
    int warp = (blockIdx.x * blockDim.x + threadIdx.x) >> 5;
    int lane = threadIdx.x & 31;
    if (warp >= n_nodes) return;

    float dv = g_dinv[warp];
    float w2 = dv * dv;
    int deg = g_cursor[warp];
    const int* crow = g_cols + (size_t)warp * CAP;

    float a0 = 0.f, a1 = 0.f, a2 = 0.f, a3 = 0.f;
    int j = 0;
    for (; j + 8 <= deg; j += 8) {
        int c[8];
#pragma unroll
        for (int k = 0; k < 8; k++) c[k] = __ldg(&crow[j + k]);
        float v[8];
#pragma unroll
        for (int k = 0; k < 8; k++) v[k] = g_dinv[c[k]];
        Half4 r[8];
#pragma unroll
        for (int k = 0; k < 8; k++) r[k] = g_y0[(size_t)c[k] * 32 + lane];
#pragma unroll
        for (int k = 0; k < 8; k++) acc_edge_w(v[k], r[k], a0, a1, a2, a3);
    }
    for (; j < deg; j++) {
        int c = __ldg(&crow[j]);
        float v = g_dinv[c];
        Half4 r = g_y0[(size_t)c * 32 + lane];
        acc_edge_w(v, r, a0, a1, a2, a3);
    }

    Half4 r;
    r.h01 = __floats2half2_rn(a0 * w2, a1 * w2);
    r.h23 = __floats2half2_rn(a2 * w2, a3 * w2);
    g_y1[(size_t)warp * 32 + lane] = r;
}

// layer 2: unweighted gather of y1; y2 = dinv^2 * sum
__global__ void __launch_bounds__(256)
spmm_l2(int n_nodes) {
    int warp = (blockIdx.x * blockDim.x + threadIdx.x) >> 5;
    int lane = threadIdx.x & 31;
    if (warp >= n_nodes) return;

    float dv = g_dinv[warp];
    float w2 = dv * dv;
    int deg = g_cursor[warp];
    const int* crow = g_cols + (size_t)warp * CAP;

    float a0 = 0.f, a1 = 0.f, a2 = 0.f, a3 = 0.f;
    gather_row(g_y1, crow, deg, lane, a0, a1, a2, a3);

    Half4 r;
    r.h01 = __floats2half2_rn(a0 * w2, a1 * w2);
    r.h23 = __floats2half2_rn(a2 * w2, a3 * w2);
    g_y2[(size_t)warp * 32 + lane] = r;
}

// layer 3: gather y2 -> x3 = dinv*sum; out = (emb + rinv*(y1+y2) + x3)/4.
// Own-row loads hoisted; cursor self-reset for next replay.
__global__ void __launch_bounds__(256)
spmm_last(const float* __restrict__ uw, const float* __restrict__ iw,
          int num_users, int n_nodes, float* __restrict__ out) {
    int warp = (blockIdx.x * blockDim.x + threadIdx.x) >> 5;
    int lane = threadIdx.x & 31;
    if (warp >= n_nodes) return;

    float dv = g_dinv[warp];
    float rv = g_rinv[warp];
    int deg = g_cursor[warp];
    if (lane == 0) g_cursor[warp] = 0;       // ready for next replay
    const int* crow = g_cols + (size_t)warp * CAP;

    // issue own-row loads early; they complete under the gather chain
    Half4 w1 = g_y1[(size_t)warp * 32 + lane];
    Half4 w2 = g_y2[(size_t)warp * 32 + lane];
    const float4* ep = (const float4*)((warp < num_users)
                          ? uw + (size_t)warp * D
                          : iw + (size_t)(warp - num_users) * D);
    float4 e = ep[lane];

    float a0 = 0.f, a1 = 0.f, a2 = 0.f, a3 = 0.f;
    gather_row(g_y2, crow, deg, lane, a0, a1, a2, a3);
    a0 *= dv; a1 *= dv; a2 *= dv; a3 *= dv;      // x3

    float2 p01 = __half22float2(w1.h01);
    float2 p23 = __half22float2(w1.h23);
    float2 q01 = __half22float2(w2.h01);
    float2 q23 = __half22float2(w2.h23);

    float4 o;
    o.x = (e.x + rv * (p01.x + q01.x) + a0) * 0.25f;
    o.y = (e.y + rv * (p01.y + q01.y) + a1) * 0.25f;
    o.z = (e.z + rv * (p23.x + q23.x) + a2) * 0.25f;
    o.w = (e.w + rv * (p23.y + q23.y) + a3) * 0.25f;
    ((float4*)(out + (size_t)warp * D))[lane] = o;
}

// --------------------------------------------------------------- launch ----

extern "C" void kernel_launch(void* const* d_in, const int* in_sizes, int n_in,
                              void* d_out, int out_size) {
    const float* uw = (const float*)d_in[0];
    const float* iw = (const float*)d_in[1];
    const int*   ei = (const int*)d_in[2];

    int num_users = in_sizes[0] / D;
    int num_items = in_sizes[1] / D;
    int n_nodes = num_users + num_items;
    int nE = in_sizes[2] / 2;
    const int* src = ei;
    const int* dst = ei + nE;
    float* out = (float*)d_out;

    // padded-CSR scatter + plain fp16 convert (cursor arrives zeroed)
    int nscat = (nE + 3) / 4;
    int total_threads = nscat + n_nodes * 32;
    scatcvt_kernel<<<(total_threads + 255) / 256, 256>>>(uw, iw, src, dst, nE,
                                                         nscat, num_users, n_nodes);
    dinv_kernel<<<(n_nodes + 255) / 256, 256>>>(n_nodes);

    // 3 propagation layers
    int blocks = (n_nodes * 32 + 255) / 256;
    spmm_l1<<<blocks, 256>>>(n_nodes);
    spmm_l2<<<blocks, 256>>>(n_nodes);
    spmm_last<<<blocks, 256>>>(uw, iw, num_users, n_nodes, out);
}

// round 17
// speedup vs baseline: 1.3653x; 1.3653x over previous
#include <cuda_runtime.h>
#include <cuda_fp16.h>

// LightGCN, y-space formulation with fp16 intermediates (dense CSR).
//   y0' = fp16(emb)  (plain — converted while hist runs)
//   y1  = dinv^2 * sum(dinv[d] * y0'[d])      (weighted layer 1)
//   y2  = dinv^2 * sum(y1[d])
//   out = (emb + rinv*(y1+y2) + dinv*sum(y2[d])) / 4, emb exact fp32.
//
// Pipeline: histcvt (REDG hist ∥ plain convert) -> scan1 -> scan23 ->
// scatter (4 edges/thread cursor atomics) -> 3 SpMM layers.
// Dense 8MB cols array (R16 lesson: padded CSR blows the L2 working set).

#define D 128
#define MAX_NODES 160000
#define MAX_EDGES 2200000
#define SCAN_BLK 1024

struct __align__(8) Half4 {
    __half2 h01;
    __half2 h23;
};

__device__ int   g_deg[MAX_NODES];          // zeroed at load; self-zeroed in scan23
__device__ int   g_rowptr[MAX_NODES + 1];
__device__ int   g_cursor[MAX_NODES];
__device__ float g_dinv[MAX_NODES];
__device__ float g_rinv[MAX_NODES];         // sqrt(deg) (0 if deg==0)
__device__ int   g_cols[MAX_EDGES];
__device__ Half4 g_y0[(size_t)MAX_NODES * 32];   // fp16(emb), plain
__device__ Half4 g_y1[(size_t)MAX_NODES * 32];
__device__ Half4 g_y2[(size_t)MAX_NODES * 32];
__device__ int   g_bsum[256];

// ---------------------------------------------------------------- setup ----

// hist (REDG, 4 edges/thread) ∥ plain fp16 convert — disjoint thread ranges.
__global__ void histcvt_kernel(const float* __restrict__ uw,
                               const float* __restrict__ iw,
                               const int* __restrict__ src,
                               int nE, int nh, int num_users, int n_nodes) {
    int i = blockIdx.x * blockDim.x + threadIdx.x;

    if (i < nh) {
        int e = i * 4;
        if (e + 3 < nE) {
            int4 s4 = __ldg((const int4*)(src + e));
            atomicAdd(&g_deg[s4.x], 1);
            atomicAdd(&g_deg[s4.y], 1);
            atomicAdd(&g_deg[s4.z], 1);
            atomicAdd(&g_deg[s4.w], 1);
        } else {
            for (int k = e; k < nE; k++) atomicAdd(&g_deg[src[k]], 1);
        }
        return;
    }

    int j = i - nh;
    if (j >= n_nodes * 32) return;
    int node = j >> 5, lane = j & 31;
    const float4* srcp = (const float4*)((node < num_users)
                            ? uw + (size_t)node * D
                            : iw + (size_t)(node - num_users) * D);
    float4 f = srcp[lane];
    Half4 r;
    r.h01 = __floats2half2_rn(f.x, f.y);
    r.h23 = __floats2half2_rn(f.z, f.w);
    g_y0[j] = r;
}

// per-1024-block exclusive scan of g_deg into g_rowptr; block sums to g_bsum
__global__ void scan1_kernel(int n) {
    __shared__ int sh[SCAN_BLK];
    int tid = threadIdx.x;
    int i = blockIdx.x * SCAN_BLK + tid;
    int v = (i < n) ? g_deg[i] : 0;
    sh[tid] = v;
    __syncthreads();
    for (int off = 1; off < SCAN_BLK; off <<= 1) {
        int t = (tid >= off) ? sh[tid - off] : 0;
        __syncthreads();
        sh[tid] += t;
        __syncthreads();
    }
    if (i < n) g_rowptr[i] = sh[tid] - v;
    if (tid == SCAN_BLK - 1) g_bsum[blockIdx.x] = sh[tid];
}

// merged scan2+scan3: block-prefix + cursor init + dinv/rinv; self-zero g_deg
__global__ void scan23_kernel(int n, int nb) {
    __shared__ int sh[256];
    int tid = threadIdx.x;
    int i = blockIdx.x * 256 + tid;
    int chunk = (blockIdx.x * 256) >> 10;          // same for whole block

    int b = (tid < nb) ? g_bsum[tid] : 0;

    sh[tid] = (tid < chunk) ? b : 0;
    __syncthreads();
    for (int off = 128; off > 0; off >>= 1) {
        if (tid < off) sh[tid] += sh[tid + off];
        __syncthreads();
    }
    int prefix = sh[0];
    __syncthreads();

    sh[tid] = b;
    __syncthreads();
    for (int off = 128; off > 0; off >>= 1) {
        if (tid < off) sh[tid] += sh[tid + off];
        __syncthreads();
    }
    int total = sh[0];

    if (i < n) {
        int rp = g_rowptr[i] + prefix;
        g_rowptr[i] = rp;
        g_cursor[i] = rp;
        int d = g_deg[i];
        float fd = (float)d;
        g_dinv[i] = (d > 0) ? rsqrtf(fd) : 0.0f;
        g_rinv[i] = (d > 0) ? sqrtf(fd) : 0.0f;
        g_deg[i] = 0;                                // ready for next replay
    }
    if (i == 0) g_rowptr[n] = total;
}

// standalone scatter: 4 edges/thread (int4), cursor atomics
__global__ void scatter_kernel(const int* __restrict__ src,
                               const int* __restrict__ dst, int nE) {
    int t = blockIdx.x * blockDim.x + threadIdx.x;
    int e = t * 4;
    if (e + 3 < nE) {
        int4 s4 = __ldg((const int4*)(src + e));
        int4 d4 = __ldg((const int4*)(dst + e));
        int p0 = atomicAdd(&g_cursor[s4.x], 1);
        int p1 = atomicAdd(&g_cursor[s4.y], 1);
        int p2 = atomicAdd(&g_cursor[s4.z], 1);
        int p3 = atomicAdd(&g_cursor[s4.w], 1);
        g_cols[p0] = d4.x;
        g_cols[p1] = d4.y;
        g_cols[p2] = d4.z;
        g_cols[p3] = d4.w;
    } else {
        for (int k = e; k < nE; k++) {
            int pos = atomicAdd(&g_cursor[src[k]], 1);
            g_cols[pos] = dst[k];
        }
    }
}

// ----------------------------------------------------------------- SpMM ----
// One warp per row; lane owns dims [4*lane, 4*lane+4) as one Half4.

__device__ __forceinline__ void acc_edge(Half4 r,
                                         float& a0, float& a1, float& a2, float& a3) {
    float2 f01 = __half22float2(r.h01);
    float2 f23 = __half22float2(r.h23);
    a0 += f01.x;
    a1 += f01.y;
    a2 += f23.x;
    a3 += f23.y;
}

__device__ __forceinline__ void acc_edge_w(float v, Half4 r,
                                           float& a0, float& a1, float& a2, float& a3) {
    float2 f01 = __half22float2(r.h01);
    float2 f23 = __half22float2(r.h23);
    a0 = fmaf(v, f01.x, a0);
    a1 = fmaf(v, f01.y, a1);
    a2 = fmaf(v, f23.x, a2);
    a3 = fmaf(v, f23.y, a3);
}

// unweighted gather (layers 2,3): 16-edge unroll
__device__ __forceinline__ void gather_row(const Half4* __restrict__ xin,
                                           int start, int end, int lane,
                                           float& a0, float& a1, float& a2, float& a3) {
    int j = start;
    for (; j + 16 <= end; j += 16) {
        int c[16];
#pragma unroll
        for (int k = 0; k < 16; k++) c[k] = __ldg(&g_cols[j + k]);
        Half4 r[16];
#pragma unroll
        for (int k = 0; k < 16; k++) r[k] = xin[(size_t)c[k] * 32 + lane];
#pragma unroll
        for (int k = 0; k < 16; k++) acc_edge(r[k], a0, a1, a2, a3);
    }
    for (; j + 4 <= end; j += 4) {
        int c0 = __ldg(&g_cols[j]);
        int c1 = __ldg(&g_cols[j + 1]);
        int c2 = __ldg(&g_cols[j + 2]);
        int c3 = __ldg(&g_cols[j + 3]);
        Half4 r0 = xin[(size_t)c0 * 32 + lane];
        Half4 r1 = xin[(size_t)c1 * 32 + lane];
        Half4 r2 = xin[(size_t)c2 * 32 + lane];
        Half4 r3 = xin[(size_t)c3 * 32 + lane];
        acc_edge(r0, a0, a1, a2, a3);
        acc_edge(r1, a0, a1, a2, a3);
        acc_edge(r2, a0, a1, a2, a3);
        acc_edge(r3, a0, a1, a2, a3);
    }
    for (; j < end; j++) {
        int c = __ldg(&g_cols[j]);
        Half4 r = xin[(size_t)c * 32 + lane];
        acc_edge(r, a0, a1, a2, a3);
    }
}

// layer 1: weighted gather of y0' (per-edge dinv); y1 = dinv^2 * sum
__global__ void __launch_bounds__(256)
spmm_l1(int n_nodes) {
    int warp = (blockIdx.x * blockDim.x + threadIdx.x) >> 5;
    int lane = threadIdx.x & 31;
    if (warp >= n_nodes) return;

    float dv = g_dinv[warp];
    float w2 = dv * dv;
    int start = __ldg(&g_rowptr[warp]);
    int end   = __ldg(&g_rowptr[warp + 1]);

    float a0 = 0.f, a1 = 0.f, a2 = 0.f, a3 = 0.f;
    int j = start;
    for (; j + 8 <= end; j += 8) {
        int c[8];
#pragma unroll
        for (int k = 0; k < 8; k++) c[k] = __ldg(&g_cols[j + k]);
        float v[8];
#pragma unroll
        for (int k = 0; k < 8; k++) v[k] = g_dinv[c[k]];
        Half4 r[8];
#pragma unroll
        for (int k = 0; k < 8; k++) r[k] = g_y0[(size_t)c[k] * 32 + lane];
#pragma unroll
        for (int k = 0; k < 8; k++) acc_edge_w(v[k], r[k], a0, a1, a2, a3);
    }
    for (; j < end; j++) {
        int c = __ldg(&g_cols[j]);
        float v = g_dinv[c];
        Half4 r = g_y0[(size_t)c * 32 + lane];
        acc_edge_w(v, r, a0, a1, a2, a3);
    }

    Half4 r;
    r.h01 = __floats2half2_rn(a0 * w2, a1 * w2);
    r.h23 = __floats2half2_rn(a2 * w2, a3 * w2);
    g_y1[(size_t)warp * 32 + lane] = r;
}

// layer 2: unweighted gather of y1; y2 = dinv^2 * sum
__global__ void __launch_bounds__(256)
spmm_l2(int n_nodes) {
    int warp = (blockIdx.x * blockDim.x + threadIdx.x) >> 5;
    int lane = threadIdx.x & 31;
    if (warp >= n_nodes) return;

    float dv = g_dinv[warp];
    float w2 = dv * dv;
    int start = __ldg(&g_rowptr[warp]);
    int end   = __ldg(&g_rowptr[warp + 1]);

    float a0 = 0.f, a1 = 0.f, a2 = 0.f, a3 = 0.f;
    gather_row(g_y1, start, end, lane, a0, a1, a2, a3);

    Half4 r;
    r.h01 = __floats2half2_rn(a0 * w2, a1 * w2);
    r.h23 = __floats2half2_rn(a2 * w2, a3 * w2);
    g_y2[(size_t)warp * 32 + lane] = r;
}

// layer 3: gather y2 -> x3 = dinv*sum; out = (emb + rinv*(y1+y2) + x3)/4.
// Own-row loads hoisted above the gather chain.
__global__ void __launch_bounds__(256)
spmm_last(const float* __restrict__ uw, const float* __restrict__ iw,
          int num_users, int n_nodes, float* __restrict__ out) {
    int warp = (blockIdx.x * blockDim.x + threadIdx.x) >> 5;
    int lane = threadIdx.x & 31;
    if (warp >= n_nodes) return;

    float dv = g_dinv[warp];
    float rv = g_rinv[warp];
    int start = __ldg(&g_rowptr[warp]);
    int end   = __ldg(&g_rowptr[warp + 1]);

    // issue own-row loads early; they complete under the gather chain
    Half4 w1 = g_y1[(size_t)warp * 32 + lane];
    Half4 w2 = g_y2[(size_t)warp * 32 + lane];
    const float4* ep = (const float4*)((warp < num_users)
                          ? uw + (size_t)warp * D
                          : iw + (size_t)(warp - num_users) * D);
    float4 e = ep[lane];

    float a0 = 0.f, a1 = 0.f, a2 = 0.f, a3 = 0.f;
    gather_row(g_y2, start, end, lane, a0, a1, a2, a3);
    a0 *= dv; a1 *= dv; a2 *= dv; a3 *= dv;      // x3

    float2 p01 = __half22float2(w1.h01);
    float2 p23 = __half22float2(w1.h23);
    float2 q01 = __half22float2(w2.h01);
    float2 q23 = __half22float2(w2.h23);

    float4 o;
    o.x = (e.x + rv * (p01.x + q01.x) + a0) * 0.25f;
    o.y = (e.y + rv * (p01.y + q01.y) + a1) * 0.25f;
    o.z = (e.z + rv * (p23.x + q23.x) + a2) * 0.25f;
    o.w = (e.w + rv * (p23.y + q23.y) + a3) * 0.25f;
    ((float4*)(out + (size_t)warp * D))[lane] = o;
}

// --------------------------------------------------------------- launch ----

extern "C" void kernel_launch(void* const* d_in, const int* in_sizes, int n_in,
                              void* d_out, int out_size) {
    const float* uw = (const float*)d_in[0];
    const float* iw = (const float*)d_in[1];
    const int*   ei = (const int*)d_in[2];

    int num_users = in_sizes[0] / D;
    int num_items = in_sizes[1] / D;
    int n_nodes = num_users + num_items;
    int nE = in_sizes[2] / 2;
    const int* src = ei;
    const int* dst = ei + nE;
    float* out = (float*)d_out;

    // hist ∥ plain convert (g_deg arrives zeroed: module init / scan23 reset)
    int nh = (nE + 3) / 4;
    int total_threads = nh + n_nodes * 32;
    histcvt_kernel<<<(total_threads + 255) / 256, 256>>>(uw, iw, src, nE, nh,
                                                         num_users, n_nodes);
    int nb = (n_nodes + SCAN_BLK - 1) / SCAN_BLK;
    scan1_kernel<<<nb, SCAN_BLK>>>(n_nodes);
    scan23_kernel<<<(n_nodes + 255) / 256, 256>>>(n_nodes, nb);
    scatter_kernel<<<((nE + 3) / 4 + 255) / 256, 256>>>(src, dst, nE);

    // 3 propagation layers
    int blocks = (n_nodes * 32 + 255) / 256;
    spmm_l1<<<blocks, 256>>>(n_nodes);
    spmm_l2<<<blocks, 256>>>(n_nodes);
    spmm_last<<<blocks, 256>>>(uw, iw, num_users, n_nodes, out);
}